// round 1
// baseline (speedup 1.0000x reference)
#include <cuda_runtime.h>
#include <cstdint>

#define SLOPE 0.15f

static const int NN = 50000;   // nodes (fixed by problem)

// ---------------- device scratch (no runtime allocation allowed) -------------
__device__ float g_cntinv[NN];                 // 1/max(deg,1)
__device__ float g_agg  [NN * 256];            // segment-sum buffer (max dim 256)
__device__ float g_mean1[NN * 128];            // mean-aggregated x
__device__ float g_h1   [NN * 512];
__device__ float g_z2   [NN * 256];
__device__ float g_r2   [NN * 256];
__device__ float g_h2   [NN * 256];
__device__ float g_z3   [NN * 64];
__device__ float g_r3   [NN * 64];
__device__ float g_h3   [NN * 64];

// ---------------- small utility kernels --------------------------------------
__global__ void zero4_kernel(float* __restrict__ p, int n4) {
    int i = blockIdx.x * blockDim.x + threadIdx.x;
    if (i < n4) ((float4*)p)[i] = make_float4(0.f, 0.f, 0.f, 0.f);
}

__global__ void count_kernel(const int* __restrict__ dst, float* __restrict__ cnt, int ne) {
    int e = blockIdx.x * blockDim.x + threadIdx.x;
    if (e < ne) atomicAdd(&cnt[dst[e]], 1.0f);
}

__global__ void invert_kernel(float* __restrict__ c, int n) {
    int i = blockIdx.x * blockDim.x + threadIdx.x;
    if (i < n) c[i] = 1.0f / fmaxf(c[i], 1.0f);
}

// vectorized global reduction add (sm_90+)
__device__ __forceinline__ void red_add_v4(float* addr, float4 v) {
    asm volatile("red.global.add.v4.f32 [%0], {%1,%2,%3,%4};"
                 :: "l"(addr), "f"(v.x), "f"(v.y), "f"(v.z), "f"(v.w) : "memory");
}

// segment-sum: out[dst] += feat[src] over edges, d4 = dim/4
__global__ void agg_kernel(const float* __restrict__ feat, const int* __restrict__ src,
                           const int* __restrict__ dst, float* __restrict__ out,
                           int d4, int ne) {
    long long idx = (long long)blockIdx.x * blockDim.x + threadIdx.x;
    long long total = (long long)ne * d4;
    if (idx >= total) return;
    int e = (int)(idx / d4);
    int c = (int)(idx % d4);
    int s = src[e], d = dst[e];
    float4 v = *(const float4*)(feat + (size_t)s * d4 * 4 + c * 4);
    red_add_v4(out + (size_t)d * d4 * 4 + c * 4, v);
}

// mean1 = agg * inv[row]
__global__ void scale_kernel(const float* __restrict__ agg, const float* __restrict__ inv,
                             float* __restrict__ out, int d4, int n) {
    int idx = blockIdx.x * blockDim.x + threadIdx.x;
    if (idx >= n * d4) return;
    int row = idx / d4;
    float iv = inv[row];
    float4 a = ((const float4*)agg)[idx];
    float4 o = make_float4(a.x * iv, a.y * iv, a.z * iv, a.w * iv);
    ((float4*)out)[idx] = o;
}

// h = leaky(agg*inv + bias + r)
__global__ void ew_kernel(const float* __restrict__ agg, const float* __restrict__ inv,
                          const float* __restrict__ r, const float* __restrict__ bias,
                          float* __restrict__ out, int d4, int n) {
    int idx = blockIdx.x * blockDim.x + threadIdx.x;
    if (idx >= n * d4) return;
    int row = idx / d4, c = idx % d4;
    float iv = inv[row];
    float4 a = ((const float4*)agg)[idx];
    float4 rr = ((const float4*)r)[idx];
    float4 b = ((const float4*)bias)[c];
    float4 o;
    o.x = fmaf(a.x, iv, b.x) + rr.x;
    o.y = fmaf(a.y, iv, b.y) + rr.y;
    o.z = fmaf(a.z, iv, b.z) + rr.z;
    o.w = fmaf(a.w, iv, b.w) + rr.w;
    o.x = o.x > 0.f ? o.x : SLOPE * o.x;
    o.y = o.y > 0.f ? o.y : SLOPE * o.y;
    o.z = o.z > 0.f ? o.z : SLOPE * o.z;
    o.w = o.w > 0.f ? o.w : SLOPE * o.w;
    ((float4*)out)[idx] = o;
}

// ---------------- tiled fp32 GEMM: C (= or +=) A[M,K] @ B[K,N] ---------------
// flags: bit0 = accumulate into C, bit1 = leaky epilogue, bit2 = add bias
#define BM 64
#define BN 64
#define BK 16
#define SST 68

__global__ __launch_bounds__(256) void gemm_kernel(
    const float* __restrict__ A, const float* __restrict__ B,
    float* __restrict__ C, const float* __restrict__ bias,
    int M, int N, int K, int flags)
{
    __shared__ float As[BK * SST];
    __shared__ float Bs[BK * SST];
    const int bm = blockIdx.y * BM;
    const int bn = blockIdx.x * BN;
    const int tid = threadIdx.x;
    const int tx = tid & 15;
    const int ty = tid >> 4;
    const int a_row = tid >> 2;          // 0..63
    const int a_col = (tid & 3) << 2;    // 0,4,8,12
    const int b_row = tid >> 4;          // 0..15
    const int b_col = (tid & 15) << 2;   // 0..60

    float acc[4][4];
#pragma unroll
    for (int i = 0; i < 4; i++)
#pragma unroll
        for (int j = 0; j < 4; j++) acc[i][j] = 0.f;

    const int gm_a = bm + a_row;
    const bool a_ok = gm_a < M;
    const float* Aptr = A + (size_t)gm_a * K + a_col;
    const float* Bptr = B + (size_t)b_row * N + bn + b_col;

    for (int k0 = 0; k0 < K; k0 += BK) {
        float4 av = make_float4(0.f, 0.f, 0.f, 0.f);
        if (a_ok) av = *(const float4*)(Aptr + k0);
        As[(a_col + 0) * SST + a_row] = av.x;
        As[(a_col + 1) * SST + a_row] = av.y;
        As[(a_col + 2) * SST + a_row] = av.z;
        As[(a_col + 3) * SST + a_row] = av.w;
        float4 bv = *(const float4*)(Bptr + (size_t)k0 * N);
        *(float4*)&Bs[b_row * SST + b_col] = bv;
        __syncthreads();
#pragma unroll
        for (int k = 0; k < BK; k++) {
            float4 a4 = *(const float4*)&As[k * SST + ty * 4];
            float4 b4 = *(const float4*)&Bs[k * SST + tx * 4];
            float a[4] = {a4.x, a4.y, a4.z, a4.w};
            float b[4] = {b4.x, b4.y, b4.z, b4.w};
#pragma unroll
            for (int i = 0; i < 4; i++)
#pragma unroll
                for (int j = 0; j < 4; j++)
                    acc[i][j] = fmaf(a[i], b[j], acc[i][j]);
        }
        __syncthreads();
    }

#pragma unroll
    for (int i = 0; i < 4; i++) {
        int gm = bm + ty * 4 + i;
        if (gm >= M) continue;
        float* crow = C + (size_t)gm * N + bn + tx * 4;
        float4 v = make_float4(acc[i][0], acc[i][1], acc[i][2], acc[i][3]);
        if (flags & 1) {
            float4 c0 = *(const float4*)crow;
            v.x += c0.x; v.y += c0.y; v.z += c0.z; v.w += c0.w;
        }
        if (flags & 4) {
            float4 bb = *(const float4*)(bias + bn + tx * 4);
            v.x += bb.x; v.y += bb.y; v.z += bb.z; v.w += bb.w;
        }
        if (flags & 2) {
            v.x = v.x > 0.f ? v.x : SLOPE * v.x;
            v.y = v.y > 0.f ? v.y : SLOPE * v.y;
            v.z = v.z > 0.f ? v.z : SLOPE * v.z;
            v.w = v.w > 0.f ? v.w : SLOPE * v.w;
        }
        *(float4*)crow = v;
    }
}

// ---------------- fused head: h3[64] -> Wp(32) -> leaky(Wf1(32)) -> Wf2(2) ----
__global__ __launch_bounds__(128) void head_kernel(
    const float* __restrict__ h3,
    const float* __restrict__ Wp, const float* __restrict__ bp,
    const float* __restrict__ Wf1, const float* __restrict__ bf1,
    const float* __restrict__ Wf2, const float* __restrict__ bf2,
    float* __restrict__ out, int n)
{
    __shared__ float sWp[64 * 32], sWf1[32 * 32], sWf2[64], sbp[32], sbf1[32], sbf2[2];
    for (int i = threadIdx.x; i < 64 * 32; i += blockDim.x) sWp[i] = Wp[i];
    for (int i = threadIdx.x; i < 32 * 32; i += blockDim.x) sWf1[i] = Wf1[i];
    for (int i = threadIdx.x; i < 64; i += blockDim.x) sWf2[i] = Wf2[i];
    if (threadIdx.x < 32) { sbp[threadIdx.x] = bp[threadIdx.x]; sbf1[threadIdx.x] = bf1[threadIdx.x]; }
    if (threadIdx.x < 2) sbf2[threadIdx.x] = bf2[threadIdx.x];
    __syncthreads();
    int nidx = blockIdx.x * blockDim.x + threadIdx.x;
    if (nidx >= n) return;

    float p[32];
#pragma unroll
    for (int j = 0; j < 32; j++) p[j] = sbp[j];
    const float* hx = h3 + (size_t)nidx * 64;
    for (int i = 0; i < 64; i++) {
        float xi = hx[i];
#pragma unroll
        for (int j = 0; j < 32; j++) p[j] = fmaf(xi, sWp[i * 32 + j], p[j]);
    }
    float q[32];
#pragma unroll
    for (int j = 0; j < 32; j++) q[j] = sbf1[j];
#pragma unroll
    for (int i = 0; i < 32; i++) {
#pragma unroll
        for (int j = 0; j < 32; j++) q[j] = fmaf(p[i], sWf1[i * 32 + j], q[j]);
    }
#pragma unroll
    for (int j = 0; j < 32; j++) q[j] = q[j] > 0.f ? q[j] : SLOPE * q[j];
    float o0 = sbf2[0], o1 = sbf2[1];
#pragma unroll
    for (int i = 0; i < 32; i++) { o0 = fmaf(q[i], sWf2[i * 2], o0); o1 = fmaf(q[i], sWf2[i * 2 + 1], o1); }
    out[(size_t)nidx * 2]     = o0;
    out[(size_t)nidx * 2 + 1] = o1;
}

// ---------------- launch ------------------------------------------------------
static inline int cdiv(long long a, int b) { return (int)((a + b - 1) / b); }

extern "C" void kernel_launch(void* const* d_in, const int* in_sizes, int n_in,
                              void* d_out, int out_size)
{
    const float* x   = (const float*)d_in[0];
    const int*   ei  = (const int*)d_in[1];
    // d_in[2] edge_attr, d_in[3] We, d_in[4] be: dead code in the reference
    const float* W1l = (const float*)d_in[5];
    const float* b1  = (const float*)d_in[6];
    const float* W1r = (const float*)d_in[7];
    const float* W2l = (const float*)d_in[8];
    const float* b2  = (const float*)d_in[9];
    const float* W2r = (const float*)d_in[10];
    const float* W3l = (const float*)d_in[11];
    const float* b3  = (const float*)d_in[12];
    const float* W3r = (const float*)d_in[13];
    const float* Wp  = (const float*)d_in[14];
    const float* bp  = (const float*)d_in[15];
    const float* Wf1 = (const float*)d_in[16];
    const float* bf1 = (const float*)d_in[17];
    const float* Wf2 = (const float*)d_in[18];
    const float* bf2 = (const float*)d_in[19];

    const int n  = in_sizes[0] / 128;   // 50000
    const int ne = in_sizes[1] / 2;     // 800000
    const int* src = ei;
    const int* dst = ei + ne;

    float *cntinv, *agg, *mean1, *h1, *z2, *r2, *h2, *z3, *r3, *h3;
    cudaGetSymbolAddress((void**)&cntinv, g_cntinv);
    cudaGetSymbolAddress((void**)&agg,    g_agg);
    cudaGetSymbolAddress((void**)&mean1,  g_mean1);
    cudaGetSymbolAddress((void**)&h1,     g_h1);
    cudaGetSymbolAddress((void**)&z2,     g_z2);
    cudaGetSymbolAddress((void**)&r2,     g_r2);
    cudaGetSymbolAddress((void**)&h2,     g_h2);
    cudaGetSymbolAddress((void**)&z3,     g_z3);
    cudaGetSymbolAddress((void**)&r3,     g_r3);
    cudaGetSymbolAddress((void**)&h3,     g_h3);
    float* out = (float*)d_out;

    const int T = 256;
    const int gM = cdiv(n, BM);

    // degree counts -> inverse
    zero4_kernel<<<cdiv(n / 4, T), T>>>(cntinv, n / 4);
    count_kernel<<<cdiv(ne, T), T>>>(dst, cntinv, ne);
    invert_kernel<<<cdiv(n, T), T>>>(cntinv, n);

    // ---- layer 1: aggregate x (dim 128), then h1 = leaky(mean@W1l + b1 + x@W1r)
    zero4_kernel<<<cdiv((long long)n * 32, T), T>>>(agg, n * 32);
    agg_kernel<<<cdiv((long long)ne * 32, T), T>>>(x, src, dst, agg, 32, ne);
    scale_kernel<<<cdiv((long long)n * 32, T), T>>>(agg, cntinv, mean1, 32, n);
    gemm_kernel<<<dim3(512 / BN, gM), T>>>(mean1, W1l, h1, nullptr, n, 512, 128, 0);
    gemm_kernel<<<dim3(512 / BN, gM), T>>>(x,     W1r, h1, b1,      n, 512, 128, 1 | 2 | 4);

    // ---- layer 2: premultiply (mean@W = mean(h@W)); aggregate in 256 dims
    gemm_kernel<<<dim3(256 / BN, gM), T>>>(h1, W2l, z2, nullptr, n, 256, 512, 0);
    gemm_kernel<<<dim3(256 / BN, gM), T>>>(h1, W2r, r2, nullptr, n, 256, 512, 0);
    zero4_kernel<<<cdiv((long long)n * 64, T), T>>>(agg, n * 64);
    agg_kernel<<<cdiv((long long)ne * 64, T), T>>>(z2, src, dst, agg, 64, ne);
    ew_kernel<<<cdiv((long long)n * 64, T), T>>>(agg, cntinv, r2, b2, h2, 64, n);

    // ---- layer 3: premultiply; aggregate in 64 dims
    gemm_kernel<<<dim3(64 / BN, gM), T>>>(h2, W3l, z3, nullptr, n, 64, 256, 0);
    gemm_kernel<<<dim3(64 / BN, gM), T>>>(h2, W3r, r3, nullptr, n, 64, 256, 0);
    zero4_kernel<<<cdiv((long long)n * 16, T), T>>>(agg, n * 16);
    agg_kernel<<<cdiv((long long)ne * 16, T), T>>>(z3, src, dst, agg, 16, ne);
    ew_kernel<<<cdiv((long long)n * 16, T), T>>>(agg, cntinv, r3, b3, h3, 16, n);

    // ---- fused head
    head_kernel<<<cdiv(n, 128), 128>>>(h3, Wp, bp, Wf1, bf1, Wf2, bf2, out, n);
}